// round 1
// baseline (speedup 1.0000x reference)
#include <cuda_runtime.h>
#include <math.h>

#define BB 8
#define NPT 2048
#define PT (BB*NPT)

// ---------------- scratch (device globals; no runtime allocation) ----------------
__device__ float g_simi[(size_t)BB*NPT*NPT];   // [B,N,M] cosine similarity
__device__ float g_xnT [(size_t)PT*128];       // normalized x3, point-major
__device__ float g_ynT [(size_t)PT*128];       // normalized y3, point-major
__device__ float g_y3t [(size_t)PT*128];       // raw y3, point-major
__device__ float g_xcat[(size_t)PT*256];       // [x3 | agg]
__device__ float g_xfull[(size_t)PT*512];      // [x1|x2|x3|x4]
__device__ float g_h5  [(size_t)PT*512];
__device__ float g_h6  [(size_t)PT*512];
__device__ float g_h7  [(size_t)PT*256];
__device__ float g_embp[(size_t)PT*128];       // emb point-major
__device__ float g_stats[BB*32*2];             // (mu, rstd) per (b, group)
__device__ float g_gsum[BB*512];
__device__ unsigned g_gmax[BB*512];

// ---------------- init (atomic accumulators must be re-zeroed every replay) ------
__global__ void zero_init_kernel() {
    int i = blockIdx.x*blockDim.x + threadIdx.x;
    if (i < BB*512) { g_gsum[i] = 0.f; g_gmax[i] = 0u; }
}

// ---------------- [B,C,N] -> point-major [B,N,dstLd] at column offset ------------
__global__ void transpose_in(const float* __restrict__ src, float* __restrict__ dst,
                             int C, int dstLd, int dstOff) {
    __shared__ float tile[32][33];
    int b  = blockIdx.z;
    int n0 = blockIdx.x*32, c0 = blockIdx.y*32;
    const float* s = src + (size_t)b*C*NPT;
    for (int i = threadIdx.y; i < 32; i += 8)
        tile[i][threadIdx.x] = s[(size_t)(c0+i)*NPT + n0 + threadIdx.x];
    __syncthreads();
    float* d = dst + (size_t)b*NPT*dstLd + dstOff;
    for (int i = threadIdx.y; i < 32; i += 8)
        d[(size_t)(n0+i)*dstLd + c0 + threadIdx.x] = tile[threadIdx.x][i];
}

// ---------------- L2-normalize 128-wide rows -------------------------------------
__global__ void norm_rows(const float* __restrict__ src, int ld, float* __restrict__ dst) {
    int p = blockIdx.x;
    int t = threadIdx.x;
    float v = src[(size_t)p*ld + t];
    float s = v*v;
    #pragma unroll
    for (int o = 16; o; o >>= 1) s += __shfl_xor_sync(0xffffffffu, s, o);
    __shared__ float ws[4];
    if ((t & 31) == 0) ws[t>>5] = s;
    __syncthreads();
    float tot = ws[0] + ws[1] + ws[2] + ws[3];
    dst[(size_t)p*128 + t] = v * rsqrtf(tot);
}

// ---------------- GEMM: C[m,n] = sum_k A[m,k]*B[n,k]  (A:[M,K], B:[N,K]) ---------
// EPI 0: raw   EPI 1: v*scale+shift then LeakyReLU(0.2)   EPI 2: v+bias
template<int EPI>
__global__ void __launch_bounds__(256) gemm_tn(
    const float* __restrict__ A, const float* __restrict__ Bw, float* __restrict__ C,
    int K, int ldc, int coff,
    size_t sA, size_t sB, size_t sC,
    const float* __restrict__ p1, const float* __restrict__ p2)
{
    __shared__ __align__(16) float As[16][132];
    __shared__ __align__(16) float Bs[16][132];
    A  += sA*blockIdx.z; Bw += sB*blockIdx.z; C += sC*blockIdx.z;
    int row0 = blockIdx.y*128, col0 = blockIdx.x*128;
    int tid = threadIdx.x;
    int tx = tid & 15, ty = tid >> 4;
    float acc[8][8];
    #pragma unroll
    for (int i = 0; i < 8; i++)
        #pragma unroll
        for (int j = 0; j < 8; j++) acc[i][j] = 0.f;

    for (int k0 = 0; k0 < K; k0 += 16) {
        #pragma unroll
        for (int i = 0; i < 2; i++) {
            int idx = tid + i*256;
            int r = idx >> 2, c4 = (idx & 3)*4;
            float4 av = *(const float4*)(A  + (size_t)(row0+r)*K + k0 + c4);
            As[c4+0][r]=av.x; As[c4+1][r]=av.y; As[c4+2][r]=av.z; As[c4+3][r]=av.w;
            float4 bv = *(const float4*)(Bw + (size_t)(col0+r)*K + k0 + c4);
            Bs[c4+0][r]=bv.x; Bs[c4+1][r]=bv.y; Bs[c4+2][r]=bv.z; Bs[c4+3][r]=bv.w;
        }
        __syncthreads();
        #pragma unroll
        for (int k = 0; k < 16; k++) {
            float4 a0 = *(const float4*)&As[k][ty*8];
            float4 a1 = *(const float4*)&As[k][ty*8+4];
            float4 b0 = *(const float4*)&Bs[k][tx*8];
            float4 b1 = *(const float4*)&Bs[k][tx*8+4];
            float a[8]  = {a0.x,a0.y,a0.z,a0.w,a1.x,a1.y,a1.z,a1.w};
            float bb[8] = {b0.x,b0.y,b0.z,b0.w,b1.x,b1.y,b1.z,b1.w};
            #pragma unroll
            for (int i = 0; i < 8; i++)
                #pragma unroll
                for (int j = 0; j < 8; j++) acc[i][j] += a[i]*bb[j];
        }
        __syncthreads();
    }

    #pragma unroll
    for (int i = 0; i < 8; i++) {
        size_t r = (size_t)(row0 + ty*8 + i);
        float* crow = C + r*ldc + coff + col0 + tx*8;
        #pragma unroll
        for (int j = 0; j < 8; j++) {
            int cc = col0 + tx*8 + j;
            float v = acc[i][j];
            if (EPI == 1) {          // BN(eval) + LeakyReLU; 1/sqrt(1+1e-5)
                v = v * (p1[cc] * 0.9999950000374998f) + p2[cc];
                v = v >= 0.f ? v : 0.2f*v;
            } else if (EPI == 2) {
                v = v + p2[cc];
            }
            crow[j] = v;
        }
    }
}

// ---------------- top-20 + softmax + neighbor aggregation ------------------------
__global__ void __launch_bounds__(256) topk_agg(const float* __restrict__ xfull,
                                                float* __restrict__ xcat)
{
    __shared__ float row[2048];
    __shared__ float tv[20]; __shared__ int tix[20];
    __shared__ float wgt[20];
    __shared__ float wmax[8]; __shared__ int wmi[8];
    int p = blockIdx.x;
    int b = p >> 11;
    const float* s = g_simi + (size_t)p*2048;
    int tid = threadIdx.x;
    for (int i = tid; i < 2048; i += 256) row[i] = s[i];
    __syncthreads();

    for (int it = 0; it < 20; it++) {
        float m = -INFINITY; int mi = 0x7fffffff;
        for (int i = tid; i < 2048; i += 256) {
            float v = row[i];
            if (v > m) { m = v; mi = i; }     // strict > keeps lowest index
        }
        #pragma unroll
        for (int o = 16; o; o >>= 1) {
            float ov = __shfl_xor_sync(0xffffffffu, m, o);
            int   oi = __shfl_xor_sync(0xffffffffu, mi, o);
            if (ov > m || (ov == m && oi < mi)) { m = ov; mi = oi; }
        }
        if ((tid & 31) == 0) { wmax[tid>>5] = m; wmi[tid>>5] = mi; }
        __syncthreads();
        if (tid == 0) {
            float bm = wmax[0]; int bi = wmi[0];
            for (int w = 1; w < 8; w++)
                if (wmax[w] > bm || (wmax[w] == bm && wmi[w] < bi)) { bm = wmax[w]; bi = wmi[w]; }
            tv[it] = bm; tix[it] = bi; row[bi] = -INFINITY;
        }
        __syncthreads();
    }

    if (tid == 0) {
        float mx = tv[0], sum = 0.f;
        float e[20];
        #pragma unroll
        for (int k = 0; k < 20; k++) { e[k] = expf(tv[k]-mx); sum += e[k]; }
        float inv = 1.f/sum;
        #pragma unroll
        for (int k = 0; k < 20; k++) wgt[k] = e[k]*inv;
    }
    __syncthreads();

    int c = tid & 127;
    float x3v = xfull[(size_t)p*512 + 128 + c];
    if (tid < 128) {
        xcat[(size_t)p*256 + c] = x3v;
    } else {
        const float* yb = g_y3t + (size_t)b*NPT*128;
        float acc = 0.f;
        #pragma unroll
        for (int k = 0; k < 20; k++) acc += wgt[k]*yb[(size_t)tix[k]*128 + c];
        // sum_k w_k (y_k - x) = sum_k w_k y_k - x   (weights sum to 1)
        xcat[(size_t)p*256 + 128 + c] = acc - x3v;
    }
}

// ---------------- GroupNorm statistics (32 groups) --------------------------------
__global__ void gn_stats_k(const float* __restrict__ x, int C, int chgShift) {
    int g = blockIdx.x, b = blockIdx.y;
    int tid = threadIdx.x;
    int chg = 1 << chgShift;
    const float* base = x + (size_t)b*NPT*C + (g << chgShift);
    int total = NPT << chgShift;
    float s = 0.f, s2 = 0.f;
    for (int i = tid; i < total; i += 256) {
        int pnt = i >> chgShift, c = i & (chg-1);
        float v = base[(size_t)pnt*C + c];
        s += v; s2 += v*v;
    }
    __shared__ float ss[256], ss2[256];
    ss[tid] = s; ss2[tid] = s2; __syncthreads();
    for (int o = 128; o; o >>= 1) {
        if (tid < o) { ss[tid] += ss[tid+o]; ss2[tid] += ss2[tid+o]; }
        __syncthreads();
    }
    if (tid == 0) {
        float cnt = (float)total;
        float mu = ss[0]/cnt;
        float var = ss2[0]/cnt - mu*mu;
        g_stats[(b*32+g)*2]   = mu;
        g_stats[(b*32+g)*2+1] = rsqrtf(var + 1e-5f);
    }
}

// ---------------- GN apply + ReLU (generic) ---------------------------------------
__global__ void gn_apply(float* __restrict__ x, const float* __restrict__ gam,
                         const float* __restrict__ bet, int Cshift, int chgShift) {
    size_t idx = (size_t)blockIdx.x*blockDim.x + threadIdx.x;
    int c = (int)(idx & ((1u<<Cshift)-1u));
    int p = (int)(idx >> Cshift);
    int b = p >> 11;
    int grp = c >> chgShift;
    float mu = g_stats[(b*32+grp)*2], rs = g_stats[(b*32+grp)*2+1];
    float v = (x[idx]-mu)*rs*gam[c] + bet[c];
    x[idx] = fmaxf(v, 0.f);
}

// ---------------- conv5 GN apply + LeakyReLU + global max/avg accumulation --------
__global__ void gn_apply5(float* __restrict__ x, const float* __restrict__ gam,
                          const float* __restrict__ bet) {
    int b = blockIdx.y;
    int p0 = blockIdx.x*128;
    int c = threadIdx.x;             // 512 threads = channels
    int grp = c >> 4;
    float mu = g_stats[(b*32+grp)*2], rs = g_stats[(b*32+grp)*2+1];
    float ga = rs*gam[c];
    float bb = bet[c] - mu*ga;
    float s = 0.f, m = -INFINITY;
    size_t base = ((size_t)b*NPT + p0)*512 + c;
    for (int p = 0; p < 128; p++) {
        size_t idx = base + (size_t)p*512;
        float v = x[idx]*ga + bb;
        v = v >= 0.f ? v : 0.2f*v;
        x[idx] = v;
        s += v; m = fmaxf(m, v);
    }
    atomicAdd(&g_gsum[b*512+c], s);
    unsigned u = __float_as_uint(m);
    u = (u & 0x80000000u) ? ~u : (u | 0x80000000u);   // order-preserving float->uint
    atomicMax(&g_gmax[b*512+c], u);
}

// ---------------- output: emb transpose to [B,128,N] -------------------------------
__global__ void emb_out(const float* __restrict__ e, float* __restrict__ dst) {
    __shared__ float tile[32][33];
    int b = blockIdx.z;
    int n0 = blockIdx.x*32, c0 = blockIdx.y*32;
    const float* s = e + (size_t)b*NPT*128;
    for (int i = threadIdx.y; i < 32; i += 8)
        tile[i][threadIdx.x] = s[(size_t)(n0+i)*128 + c0 + threadIdx.x];
    __syncthreads();
    float* d = dst + (size_t)b*128*NPT;
    for (int i = threadIdx.y; i < 32; i += 8)
        d[(size_t)(c0+i)*NPT + n0 + threadIdx.x] = tile[threadIdx.x][i];
}

// ---------------- output: global vector [B,1024] -----------------------------------
__global__ void gv_out(float* __restrict__ dst) {
    int i = blockIdx.x*blockDim.x + threadIdx.x;   // 8192
    int b = i >> 10, c = i & 1023;
    float v;
    if (c < 512) {
        unsigned u = g_gmax[b*512+c];
        unsigned f = (u & 0x80000000u) ? (u ^ 0x80000000u) : ~u;
        v = __uint_as_float(f);
    } else {
        v = g_gsum[b*512 + c - 512] * (1.f/2048.f);
    }
    dst[i] = v;
}

// ===================================================================================
extern "C" void kernel_launch(void* const* d_in, const int* in_sizes, int n_in,
                              void* d_out, int out_size) {
    const float* x1   = (const float*)d_in[0];
    const float* x2   = (const float*)d_in[1];
    const float* x3   = (const float*)d_in[2];
    const float* y3   = (const float*)d_in[3];
    const float* w4   = (const float*)d_in[4];
    const float* bn4g = (const float*)d_in[5];
    const float* bn4b = (const float*)d_in[6];
    const float* w5   = (const float*)d_in[7];
    const float* gn5g = (const float*)d_in[8];
    const float* gn5b = (const float*)d_in[9];
    const float* wm1  = (const float*)d_in[10];
    const float* bm1  = (const float*)d_in[11];
    const float* gn6g = (const float*)d_in[12];
    const float* gn6b = (const float*)d_in[13];
    const float* wm2  = (const float*)d_in[14];
    const float* bm2  = (const float*)d_in[15];
    const float* gn7g = (const float*)d_in[16];
    const float* gn7b = (const float*)d_in[17];
    const float* wm3  = (const float*)d_in[18];
    const float* bm3  = (const float*)d_in[19];
    const float* gn8g = (const float*)d_in[20];
    const float* gn8b = (const float*)d_in[21];
    float* out = (float*)d_out;

    float *simi, *xnT, *ynT, *y3t, *xcat, *xfull, *h5, *h6, *h7, *embp;
    cudaGetSymbolAddress((void**)&simi,  g_simi);
    cudaGetSymbolAddress((void**)&xnT,   g_xnT);
    cudaGetSymbolAddress((void**)&ynT,   g_ynT);
    cudaGetSymbolAddress((void**)&y3t,   g_y3t);
    cudaGetSymbolAddress((void**)&xcat,  g_xcat);
    cudaGetSymbolAddress((void**)&xfull, g_xfull);
    cudaGetSymbolAddress((void**)&h5,    g_h5);
    cudaGetSymbolAddress((void**)&h6,    g_h6);
    cudaGetSymbolAddress((void**)&h7,    g_h7);
    cudaGetSymbolAddress((void**)&embp,  g_embp);

    dim3 tb(32, 8);

    zero_init_kernel<<<16, 256>>>();

    // transposes to point-major; x1|x2|x3 land directly inside xfull
    transpose_in<<<dim3(64,2,8), tb>>>(x1, xfull, 64, 512, 0);
    transpose_in<<<dim3(64,2,8), tb>>>(x2, xfull, 64, 512, 64);
    transpose_in<<<dim3(64,4,8), tb>>>(x3, xfull, 128, 512, 128);
    transpose_in<<<dim3(64,4,8), tb>>>(y3, y3t, 128, 128, 0);

    norm_rows<<<PT, 128>>>(xfull + 128, 512, xnT);
    norm_rows<<<PT, 128>>>(y3t, 128, ynT);

    // cosine similarity: per-batch [2048 x 2048 x 128]
    gemm_tn<0><<<dim3(16,16,8), 256>>>(xnT, ynT, simi, 128, 2048, 0,
                                       (size_t)NPT*128, (size_t)NPT*128, (size_t)NPT*NPT,
                                       nullptr, nullptr);

    // top-20 + softmax + aggregation -> xcat [P,256]
    topk_agg<<<PT, 256>>>(xfull, xcat);

    // conv4 (BN eval + lrelu) -> xfull cols [256..512)
    gemm_tn<1><<<dim3(2,128,1), 256>>>(xcat, w4, xfull, 256, 512, 256, 0,0,0, bn4g, bn4b);

    // conv5 raw
    gemm_tn<0><<<dim3(4,128,1), 256>>>(xfull, w5, h5, 512, 512, 0, 0,0,0, nullptr, nullptr);
    gn_stats_k<<<dim3(32,8), 256>>>(h5, 512, 4);
    gn_apply5 <<<dim3(16,8), 512>>>(h5, gn5g, gn5b);      // lrelu + gmax/gavg

    // mlp conv1
    gemm_tn<2><<<dim3(4,128,1), 256>>>(h5, wm1, h6, 512, 512, 0, 0,0,0, nullptr, bm1);
    gn_stats_k<<<dim3(32,8), 256>>>(h6, 512, 4);
    gn_apply  <<<32768, 256>>>(h6, gn6g, gn6b, 9, 4);

    // mlp conv2
    gemm_tn<2><<<dim3(2,128,1), 256>>>(h6, wm2, h7, 512, 256, 0, 0,0,0, nullptr, bm2);
    gn_stats_k<<<dim3(32,8), 256>>>(h7, 256, 3);
    gn_apply  <<<16384, 256>>>(h7, gn7g, gn7b, 8, 3);

    // mlp conv3
    gemm_tn<2><<<dim3(1,128,1), 256>>>(h7, wm3, embp, 256, 128, 0, 0,0,0, nullptr, bm3);
    gn_stats_k<<<dim3(32,8), 256>>>(embp, 128, 2);
    gn_apply  <<<8192, 256>>>(embp, gn8g, gn8b, 7, 2);

    // outputs
    emb_out<<<dim3(64,4,8), tb>>>(embp, out);
    gv_out <<<8, 1024>>>(out + (size_t)BB*128*NPT);
}

// round 3
// speedup vs baseline: 1.6882x; 1.6882x over previous
#include <cuda_runtime.h>
#include <cuda_bf16.h>
#include <math.h>

#define BB 8
#define NPT 2048
#define PT (BB*NPT)

// ---------------- scratch (device globals; no runtime allocation) ----------------
__device__ float g_simi[(size_t)BB*NPT*NPT];   // [B,N,M] cosine similarity
__device__ float g_xnT [(size_t)PT*128];       // normalized x3, point-major
__device__ float g_ynT [(size_t)PT*128];       // normalized y3, point-major
__device__ float g_y3t [(size_t)PT*128];       // raw y3, point-major
__device__ float g_xcat[(size_t)PT*256];       // [x3 | agg]
__device__ float g_xfull[(size_t)PT*512];      // [x1|x2|x3|x4]
__device__ float g_h5  [(size_t)PT*512];
__device__ float g_h6  [(size_t)PT*512];
__device__ float g_h7  [(size_t)PT*256];
__device__ float g_embp[(size_t)PT*128];       // emb point-major
__device__ float g_stats[BB*32*2];             // (mu, rstd) per (b, group)
__device__ float g_gsum[BB*512];
__device__ unsigned g_gmax[BB*512];

// ---------------- init (atomic accumulators must be re-zeroed every replay) ------
__global__ void zero_init_kernel() {
    int i = blockIdx.x*blockDim.x + threadIdx.x;
    if (i < BB*512) { g_gsum[i] = 0.f; g_gmax[i] = 0u; }
}

// ---------------- [B,C,N] -> point-major [B,N,dstLd] at column offset ------------
__global__ void transpose_in(const float* __restrict__ src, float* __restrict__ dst,
                             int C, int dstLd, int dstOff) {
    __shared__ float tile[32][33];
    int b  = blockIdx.z;
    int n0 = blockIdx.x*32, c0 = blockIdx.y*32;
    const float* s = src + (size_t)b*C*NPT;
    for (int i = threadIdx.y; i < 32; i += 8)
        tile[i][threadIdx.x] = s[(size_t)(c0+i)*NPT + n0 + threadIdx.x];
    __syncthreads();
    float* d = dst + (size_t)b*NPT*dstLd + dstOff;
    for (int i = threadIdx.y; i < 32; i += 8)
        d[(size_t)(n0+i)*dstLd + c0 + threadIdx.x] = tile[threadIdx.x][i];
}

// ---------------- L2-normalize 128-wide rows -------------------------------------
__global__ void norm_rows(const float* __restrict__ src, int ld, float* __restrict__ dst) {
    int p = blockIdx.x;
    int t = threadIdx.x;
    float v = src[(size_t)p*ld + t];
    float s = v*v;
    #pragma unroll
    for (int o = 16; o; o >>= 1) s += __shfl_xor_sync(0xffffffffu, s, o);
    __shared__ float ws[4];
    if ((t & 31) == 0) ws[t>>5] = s;
    __syncthreads();
    float tot = ws[0] + ws[1] + ws[2] + ws[3];
    dst[(size_t)p*128 + t] = v * rsqrtf(tot);
}

// ---------------- bf16 hi/lo split, packing 2 consecutive k values per uint32 ----
__device__ __forceinline__ void split2(float a, float b, unsigned& hi, unsigned& lo) {
    __nv_bfloat162 h = __floats2bfloat162_rn(a, b);
    float ra = a - __bfloat162float(h.x);
    float rb = b - __bfloat162float(h.y);
    __nv_bfloat162 l = __floats2bfloat162_rn(ra, rb);
    hi = *reinterpret_cast<unsigned*>(&h);
    lo = *reinterpret_cast<unsigned*>(&l);
}

#define MMA_BF16(ACC, AF, BF) \
    asm volatile( \
        "mma.sync.aligned.m16n8k16.row.col.f32.bf16.bf16.f32 " \
        "{%0,%1,%2,%3}, {%4,%5,%6,%7}, {%8,%9}, {%0,%1,%2,%3};" \
        : "+f"(ACC[0]), "+f"(ACC[1]), "+f"(ACC[2]), "+f"(ACC[3]) \
        : "r"(AF[0]), "r"(AF[1]), "r"(AF[2]), "r"(AF[3]), \
          "r"(BF[0]), "r"(BF[1]))

// ---------------- bf16x3 tensor-core GEMM: C[m,n] = sum_k A[m,k]*B[n,k] ----------
// A:[M,K] row-major, B:[N,K] row-major. fp32-grade accuracy via hi/lo split:
//   acc += Ahi*Bhi + Ahi*Blo + Alo*Bhi   (lo*lo dropped, ~2^-18 relative)
// Block tile 128x128x32, 8 warps (2M x 4N), warp tile 64x32, mma m16n8k16.
// EPI 0: raw   EPI 1: v*scale+shift then LeakyReLU(0.2)   EPI 2: v+bias
template<int EPI>
__global__ void __launch_bounds__(256) gemm_mma(
    const float* __restrict__ A, const float* __restrict__ Bw, float* __restrict__ C,
    int K, int ldc, int coff,
    size_t sA, size_t sB, size_t sC,
    const float* __restrict__ p1, const float* __restrict__ p2)
{
    // [mn][k2] layout in uint32 (2 bf16 per uint), row stride 20 -> conflict-free
    __shared__ __align__(16) unsigned Ah[128*20], Al[128*20];
    __shared__ __align__(16) unsigned Bh[128*20], Bl[128*20];
    A  += sA*blockIdx.z; Bw += sB*blockIdx.z; C += sC*blockIdx.z;
    const int row0 = blockIdx.y*128, col0 = blockIdx.x*128;
    const int tid  = threadIdx.x;
    const int lane = tid & 31, warp = tid >> 5;
    const int warpM = warp & 1, warpN = warp >> 1;     // 2 x 4 warp grid

    float acc[4][4][4];
    #pragma unroll
    for (int mi = 0; mi < 4; mi++)
        #pragma unroll
        for (int ni = 0; ni < 4; ni++)
            #pragma unroll
            for (int q = 0; q < 4; q++) acc[mi][ni][q] = 0.f;

    float4 ra[4], rb[4];
    // global-load map: linear = tid + i*256 ; row = linear/8 ; k4 = (linear%8)*4
    #pragma unroll
    for (int i = 0; i < 4; i++) {
        int lin = tid + i*256;
        int r = lin >> 3, kq = (lin & 7) << 2;
        ra[i] = *(const float4*)(A  + (size_t)(row0 + r)*K + kq);
        rb[i] = *(const float4*)(Bw + (size_t)(col0 + r)*K + kq);
    }

    const int nk = K >> 5;      // 32 k-values per tile
    for (int t = 0; t < nk; t++) {
        __syncthreads();
        #pragma unroll
        for (int i = 0; i < 4; i++) {
            int lin = tid + i*256;
            int r = lin >> 3, c2 = (lin & 7) << 1;    // uint col (2 k per uint)
            unsigned h0,l0,h1,l1;
            split2(ra[i].x, ra[i].y, h0, l0);
            split2(ra[i].z, ra[i].w, h1, l1);
            Ah[r*20 + c2] = h0; Ah[r*20 + c2 + 1] = h1;
            Al[r*20 + c2] = l0; Al[r*20 + c2 + 1] = l1;
            split2(rb[i].x, rb[i].y, h0, l0);
            split2(rb[i].z, rb[i].w, h1, l1);
            Bh[r*20 + c2] = h0; Bh[r*20 + c2 + 1] = h1;
            Bl[r*20 + c2] = l0; Bl[r*20 + c2 + 1] = l1;
        }
        __syncthreads();
        if (t + 1 < nk) {
            int k0 = (t + 1) << 5;
            #pragma unroll
            for (int i = 0; i < 4; i++) {
                int lin = tid + i*256;
                int r = lin >> 3, kq = (lin & 7) << 2;
                ra[i] = *(const float4*)(A  + (size_t)(row0 + r)*K + k0 + kq);
                rb[i] = *(const float4*)(Bw + (size_t)(col0 + r)*K + k0 + kq);
            }
        }
        #pragma unroll
        for (int kk = 0; kk < 2; kk++) {           // two k16 chunks per tile
            const int kb = kk*8;
            unsigned ah[4][4], al[4][4], bh[4][2], bl[4][2];
            #pragma unroll
            for (int mi = 0; mi < 4; mi++) {
                int r = warpM*64 + mi*16 + (lane >> 2);
                int c = kb + (lane & 3);
                ah[mi][0] = Ah[r*20 + c];       al[mi][0] = Al[r*20 + c];
                ah[mi][1] = Ah[(r+8)*20 + c];   al[mi][1] = Al[(r+8)*20 + c];
                ah[mi][2] = Ah[r*20 + c + 4];   al[mi][2] = Al[r*20 + c + 4];
                ah[mi][3] = Ah[(r+8)*20 + c+4]; al[mi][3] = Al[(r+8)*20 + c+4];
            }
            #pragma unroll
            for (int ni = 0; ni < 4; ni++) {
                int n = warpN*32 + ni*8 + (lane >> 2);
                int c = kb + (lane & 3);
                bh[ni][0] = Bh[n*20 + c];       bl[ni][0] = Bl[n*20 + c];
                bh[ni][1] = Bh[n*20 + c + 4];   bl[ni][1] = Bl[n*20 + c + 4];
            }
            #pragma unroll
            for (int mi = 0; mi < 4; mi++)
                #pragma unroll
                for (int ni = 0; ni < 4; ni++) {
                    MMA_BF16(acc[mi][ni], ah[mi], bh[ni]);
                    MMA_BF16(acc[mi][ni], ah[mi], bl[ni]);
                    MMA_BF16(acc[mi][ni], al[mi], bh[ni]);
                }
        }
    }

    // epilogue: c0,c1 -> (row, col..col+1); c2,c3 -> (row+8, col..col+1)
    #pragma unroll
    for (int mi = 0; mi < 4; mi++) {
        int r = row0 + warpM*64 + mi*16 + (lane >> 2);
        #pragma unroll
        for (int ni = 0; ni < 4; ni++) {
            int cc = col0 + warpN*32 + ni*8 + (lane & 3)*2;
            #pragma unroll
            for (int half = 0; half < 2; half++) {
                int rr = r + half*8;
                float v0 = acc[mi][ni][half*2 + 0];
                float v1 = acc[mi][ni][half*2 + 1];
                if (EPI == 1) {      // BN(eval) + LeakyReLU; 1/sqrt(1+1e-5)
                    v0 = v0 * (p1[cc]   * 0.9999950000374998f) + p2[cc];
                    v1 = v1 * (p1[cc+1] * 0.9999950000374998f) + p2[cc+1];
                    v0 = v0 >= 0.f ? v0 : 0.2f*v0;
                    v1 = v1 >= 0.f ? v1 : 0.2f*v1;
                } else if (EPI == 2) {
                    v0 += p2[cc]; v1 += p2[cc+1];
                }
                *(float2*)(C + (size_t)rr*ldc + coff + cc) = make_float2(v0, v1);
            }
        }
    }
}

// ---------------- top-20 + softmax + neighbor aggregation ------------------------
__global__ void __launch_bounds__(256) topk_agg(const float* __restrict__ xfull,
                                                float* __restrict__ xcat)
{
    __shared__ float row[2048];
    __shared__ float tv[20]; __shared__ int tix[20];
    __shared__ float wgt[20];
    __shared__ float wmax[8]; __shared__ int wmi[8];
    int p = blockIdx.x;
    int b = p >> 11;
    const float* s = g_simi + (size_t)p*2048;
    int tid = threadIdx.x;
    for (int i = tid; i < 2048; i += 256) row[i] = s[i];
    __syncthreads();

    for (int it = 0; it < 20; it++) {
        float m = -INFINITY; int mi = 0x7fffffff;
        for (int i = tid; i < 2048; i += 256) {
            float v = row[i];
            if (v > m) { m = v; mi = i; }     // strict > keeps lowest index
        }
        #pragma unroll
        for (int o = 16; o; o >>= 1) {
            float ov = __shfl_xor_sync(0xffffffffu, m, o);
            int   oi = __shfl_xor_sync(0xffffffffu, mi, o);
            if (ov > m || (ov == m && oi < mi)) { m = ov; mi = oi; }
        }
        if ((tid & 31) == 0) { wmax[tid>>5] = m; wmi[tid>>5] = mi; }
        __syncthreads();
        if (tid == 0) {
            float bm = wmax[0]; int bi = wmi[0];
            for (int w = 1; w < 8; w++)
                if (wmax[w] > bm || (wmax[w] == bm && wmi[w] < bi)) { bm = wmax[w]; bi = wmi[w]; }
            tv[it] = bm; tix[it] = bi; row[bi] = -INFINITY;
        }
        __syncthreads();
    }

    if (tid == 0) {
        float mx = tv[0], sum = 0.f;
        float e[20];
        #pragma unroll
        for (int k = 0; k < 20; k++) { e[k] = expf(tv[k]-mx); sum += e[k]; }
        float inv = 1.f/sum;
        #pragma unroll
        for (int k = 0; k < 20; k++) wgt[k] = e[k]*inv;
    }
    __syncthreads();

    int c = tid & 127;
    float x3v = xfull[(size_t)p*512 + 128 + c];
    if (tid < 128) {
        xcat[(size_t)p*256 + c] = x3v;
    } else {
        const float* yb = g_y3t + (size_t)b*NPT*128;
        float acc = 0.f;
        #pragma unroll
        for (int k = 0; k < 20; k++) acc += wgt[k]*yb[(size_t)tix[k]*128 + c];
        // sum_k w_k (y_k - x) = sum_k w_k y_k - x   (weights sum to 1)
        xcat[(size_t)p*256 + 128 + c] = acc - x3v;
    }
}

// ---------------- GroupNorm statistics (32 groups) --------------------------------
__global__ void gn_stats_k(const float* __restrict__ x, int C, int chgShift) {
    int g = blockIdx.x, b = blockIdx.y;
    int tid = threadIdx.x;
    int chg = 1 << chgShift;
    const float* base = x + (size_t)b*NPT*C + (g << chgShift);
    int total = NPT << chgShift;
    float s = 0.f, s2 = 0.f;
    for (int i = tid; i < total; i += 256) {
        int pnt = i >> chgShift, c = i & (chg-1);
        float v = base[(size_t)pnt*C + c];
        s += v; s2 += v*v;
    }
    __shared__ float ss[256], ss2[256];
    ss[tid] = s; ss2[tid] = s2; __syncthreads();
    for (int o = 128; o; o >>= 1) {
        if (tid < o) { ss[tid] += ss[tid+o]; ss2[tid] += ss2[tid+o]; }
        __syncthreads();
    }
    if (tid == 0) {
        float cnt = (float)total;
        float mu = ss[0]/cnt;
        float var = ss2[0]/cnt - mu*mu;
        g_stats[(b*32+g)*2]   = mu;
        g_stats[(b*32+g)*2+1] = rsqrtf(var + 1e-5f);
    }
}

// ---------------- GN apply + ReLU (generic) ---------------------------------------
__global__ void gn_apply(float* __restrict__ x, const float* __restrict__ gam,
                         const float* __restrict__ bet, int Cshift, int chgShift) {
    size_t idx = (size_t)blockIdx.x*blockDim.x + threadIdx.x;
    int c = (int)(idx & ((1u<<Cshift)-1u));
    int p = (int)(idx >> Cshift);
    int b = p >> 11;
    int grp = c >> chgShift;
    float mu = g_stats[(b*32+grp)*2], rs = g_stats[(b*32+grp)*2+1];
    float v = (x[idx]-mu)*rs*gam[c] + bet[c];
    x[idx] = fmaxf(v, 0.f);
}

// ---------------- conv5 GN apply + LeakyReLU + global max/avg accumulation --------
__global__ void gn_apply5(float* __restrict__ x, const float* __restrict__ gam,
                          const float* __restrict__ bet) {
    int b = blockIdx.y;
    int p0 = blockIdx.x*128;
    int c = threadIdx.x;             // 512 threads = channels
    int grp = c >> 4;
    float mu = g_stats[(b*32+grp)*2], rs = g_stats[(b*32+grp)*2+1];
    float ga = rs*gam[c];
    float bb = bet[c] - mu*ga;
    float s = 0.f, m = -INFINITY;
    size_t base = ((size_t)b*NPT + p0)*512 + c;
    for (int p = 0; p < 128; p++) {
        size_t idx = base + (size_t)p*512;
        float v = x[idx]*ga + bb;
        v = v >= 0.f ? v : 0.2f*v;
        x[idx] = v;
        s += v; m = fmaxf(m, v);
    }
    atomicAdd(&g_gsum[b*512+c], s);
    unsigned u = __float_as_uint(m);
    u = (u & 0x80000000u) ? ~u : (u | 0x80000000u);   // order-preserving float->uint
    atomicMax(&g_gmax[b*512+c], u);
}

// ---------------- output: emb transpose to [B,128,N] -------------------------------
__global__ void emb_out(const float* __restrict__ e, float* __restrict__ dst) {
    __shared__ float tile[32][33];
    int b = blockIdx.z;
    int n0 = blockIdx.x*32, c0 = blockIdx.y*32;
    const float* s = e + (size_t)b*NPT*128;
    for (int i = threadIdx.y; i < 32; i += 8)
        tile[i][threadIdx.x] = s[(size_t)(n0+i)*128 + c0 + threadIdx.x];
    __syncthreads();
    float* d = dst + (size_t)b*128*NPT;
    for (int i = threadIdx.y; i < 32; i += 8)
        d[(size_t)(c0+i)*NPT + n0 + threadIdx.x] = tile[threadIdx.x][i];
}

// ---------------- output: global vector [B,1024] -----------------------------------
__global__ void gv_out(float* __restrict__ dst) {
    int i = blockIdx.x*blockDim.x + threadIdx.x;   // 8192
    int b = i >> 10, c = i & 1023;
    float v;
    if (c < 512) {
        unsigned u = g_gmax[b*512+c];
        unsigned f = (u & 0x80000000u) ? (u ^ 0x80000000u) : ~u;
        v = __uint_as_float(f);
    } else {
        v = g_gsum[b*512 + c - 512] * (1.f/2048.f);
    }
    dst[i] = v;
}

// ===================================================================================
extern "C" void kernel_launch(void* const* d_in, const int* in_sizes, int n_in,
                              void* d_out, int out_size) {
    const float* x1   = (const float*)d_in[0];
    const float* x2   = (const float*)d_in[1];
    const float* x3   = (const float*)d_in[2];
    const float* y3   = (const float*)d_in[3];
    const float* w4   = (const float*)d_in[4];
    const float* bn4g = (const float*)d_in[5];
    const float* bn4b = (const float*)d_in[6];
    const float* w5   = (const float*)d_in[7];
    const float* gn5g = (const float*)d_in[8];
    const float* gn5b = (const float*)d_in[9];
    const float* wm1  = (const float*)d_in[10];
    const float* bm1  = (const float*)d_in[11];
    const float* gn6g = (const float*)d_in[12];
    const float* gn6b = (const float*)d_in[13];
    const float* wm2  = (const float*)d_in[14];
    const float* bm2  = (const float*)d_in[15];
    const float* gn7g = (const float*)d_in[16];
    const float* gn7b = (const float*)d_in[17];
    const float* wm3  = (const float*)d_in[18];
    const float* bm3  = (const float*)d_in[19];
    const float* gn8g = (const float*)d_in[20];
    const float* gn8b = (const float*)d_in[21];
    float* out = (float*)d_out;

    float *simi, *xnT, *ynT, *y3t, *xcat, *xfull, *h5, *h6, *h7, *embp;
    cudaGetSymbolAddress((void**)&simi,  g_simi);
    cudaGetSymbolAddress((void**)&xnT,   g_xnT);
    cudaGetSymbolAddress((void**)&ynT,   g_ynT);
    cudaGetSymbolAddress((void**)&y3t,   g_y3t);
    cudaGetSymbolAddress((void**)&xcat,  g_xcat);
    cudaGetSymbolAddress((void**)&xfull, g_xfull);
    cudaGetSymbolAddress((void**)&h5,    g_h5);
    cudaGetSymbolAddress((void**)&h6,    g_h6);
    cudaGetSymbolAddress((void**)&h7,    g_h7);
    cudaGetSymbolAddress((void**)&embp,  g_embp);

    dim3 tb(32, 8);

    zero_init_kernel<<<16, 256>>>();

    // transposes to point-major; x1|x2|x3 land directly inside xfull
    transpose_in<<<dim3(64,2,8), tb>>>(x1, xfull, 64, 512, 0);
    transpose_in<<<dim3(64,2,8), tb>>>(x2, xfull, 64, 512, 64);
    transpose_in<<<dim3(64,4,8), tb>>>(x3, xfull, 128, 512, 128);
    transpose_in<<<dim3(64,4,8), tb>>>(y3, y3t, 128, 128, 0);

    norm_rows<<<PT, 128>>>(xfull + 128, 512, xnT);
    norm_rows<<<PT, 128>>>(y3t, 128, ynT);

    // cosine similarity: per-batch [2048 x 2048 x 128], bf16x3 tensor cores
    gemm_mma<0><<<dim3(16,16,8), 256>>>(xnT, ynT, simi, 128, 2048, 0,
                                        (size_t)NPT*128, (size_t)NPT*128, (size_t)NPT*NPT,
                                        nullptr, nullptr);

    // top-20 + softmax + aggregation -> xcat [P,256]
    topk_agg<<<PT, 256>>>(xfull, xcat);

    // conv4 (BN eval + lrelu) -> xfull cols [256..512)
    gemm_mma<1><<<dim3(2,128,1), 256>>>(xcat, w4, xfull, 256, 512, 256, 0,0,0, bn4g, bn4b);

    // conv5 raw
    gemm_mma<0><<<dim3(4,128,1), 256>>>(xfull, w5, h5, 512, 512, 0, 0,0,0, nullptr, nullptr);
    gn_stats_k<<<dim3(32,8), 256>>>(h5, 512, 4);
    gn_apply5 <<<dim3(16,8), 512>>>(h5, gn5g, gn5b);      // lrelu + gmax/gavg

    // mlp conv1
    gemm_mma<2><<<dim3(4,128,1), 256>>>(h5, wm1, h6, 512, 512, 0, 0,0,0, nullptr, bm1);
    gn_stats_k<<<dim3(32,8), 256>>>(h6, 512, 4);
    gn_apply  <<<32768, 256>>>(h6, gn6g, gn6b, 9, 4);

    // mlp conv2
    gemm_mma<2><<<dim3(2,128,1), 256>>>(h6, wm2, h7, 512, 256, 0, 0,0,0, nullptr, bm2);
    gn_stats_k<<<dim3(32,8), 256>>>(h7, 256, 3);
    gn_apply  <<<16384, 256>>>(h7, gn7g, gn7b, 8, 3);

    // mlp conv3
    gemm_mma<2><<<dim3(1,128,1), 256>>>(h7, wm3, embp, 256, 128, 0, 0,0,0, nullptr, bm3);
    gn_stats_k<<<dim3(32,8), 256>>>(embp, 128, 2);
    gn_apply  <<<8192, 256>>>(embp, gn8g, gn8b, 7, 2);

    // outputs
    emb_out<<<dim3(64,4,8), tb>>>(embp, out);
    gv_out <<<8, 1024>>>(out + (size_t)BB*128*NPT);
}